// round 16
// baseline (speedup 1.0000x reference)
#include <cuda_runtime.h>
#include <cstdint>

#define U_ 128
#define C_ 64
#define B_ 16
#define T_ 128
#define RANKS 8          // CTAs per cluster (one cluster per batch)
#define JPC 16           // post-neurons owned per CTA
#define IPL 8            // pre-neurons per lane (128 / 16)
#define CPL 4            // sensory channels per lane (64 / 16)
#define NTH 256
#define UNFOLDS 6
#define EPS_ 1e-8f
#define TX_V 512u        // bytes per v-set arriving at each CTA: 128 msgs * 4B
#define FXS 2097152.0f   // 2^21 fixed-point scale (cancels in num/den ratio)

// ---------------- device scratch (no allocations allowed) ----------------
__device__ float g_rsK[U_*U_];   //  sigma * 0.5
__device__ float g_rcK[U_*U_];   // -sigma * mu * 0.5
__device__ float g_rwE[U_*U_];   //  softplus(w) * erev * 0.5
__device__ float g_ssK[C_*U_];   //  ssigma * iw * 0.5
__device__ float g_scK[C_*U_];   //  ssigma * (ib - smu) * 0.5
__device__ float g_swE[C_*U_];   //  softplus(sw) * serev * 0.5
__device__ float g_cmt[U_];      //  softplus(cm) * 6
__device__ float g_AA[U_];       //  cmt + softplus(gleak)
__device__ float g_CC[U_];       //  softplus(gleak) * vleak

__device__ __forceinline__ float softplus_f(float x) {
    return fmaxf(x, 0.0f) + log1pf(expf(-fabsf(x)));
}

__global__ void ltc_prep(const float* __restrict__ sigma, const float* __restrict__ mu,
                         const float* __restrict__ w,     const float* __restrict__ erev,
                         const float* __restrict__ ssig,  const float* __restrict__ smu,
                         const float* __restrict__ sw,    const float* __restrict__ serev,
                         const float* __restrict__ iw,    const float* __restrict__ ib,
                         const float* __restrict__ gleak, const float* __restrict__ vleak,
                         const float* __restrict__ cm)
{
    int idx = blockIdx.x * blockDim.x + threadIdx.x;
    if (idx < U_*U_) {
        float sg = sigma[idx];
        g_rsK[idx] =  sg * 0.5f;
        g_rcK[idx] = -sg * mu[idx] * 0.5f;
        g_rwE[idx] =  softplus_f(w[idx]) * erev[idx] * 0.5f;
    }
    if (idx < C_*U_) {
        int c = idx / U_;
        float sg = ssig[idx];
        g_ssK[idx] = sg * iw[c] * 0.5f;
        g_scK[idx] = sg * (ib[c] - smu[idx]) * 0.5f;
        g_swE[idx] = softplus_f(sw[idx]) * serev[idx] * 0.5f;
    }
    if (idx < U_) {
        float gl  = softplus_f(gleak[idx]);
        float cmt = softplus_f(cm[idx]) * (float)UNFOLDS;
        g_cmt[idx] = cmt;
        g_AA[idx]  = cmt + gl;
        g_CC[idx]  = gl * vleak[idx];
    }
}

// ---------------- PTX helpers ----------------
__device__ __forceinline__ uint32_t smem_u32(const void* p) {
    uint32_t a;
    asm("{ .reg .u64 t; cvta.to.shared.u64 t, %1; cvt.u32.u64 %0, t; }" : "=r"(a) : "l"(p));
    return a;
}
__device__ __forceinline__ uint32_t mapa_u32(uint32_t a, uint32_t r) {
    uint32_t o;
    asm("mapa.shared::cluster.u32 %0, %1, %2;" : "=r"(o) : "r"(a), "r"(r));
    return o;
}
__device__ __forceinline__ void cluster_sync_() {
    asm volatile("barrier.cluster.arrive.aligned;" ::: "memory");
    asm volatile("barrier.cluster.wait.aligned;"   ::: "memory");
}
__device__ __forceinline__ float tanhf_a(float x) { float y; asm("tanh.approx.f32 %0, %1;" : "=f"(y) : "f"(x)); return y; }
__device__ __forceinline__ float rcpf_(float x)   { float y; asm("rcp.approx.f32 %0, %1;"  : "=f"(y) : "f"(x)); return y; }
// s32 warp-segment reduction (HW REDUX, sm_80+)
__device__ __forceinline__ int redux_add_s32(int v, uint32_t mask) {
    int r;
    asm volatile("redux.sync.add.s32 %0, %1, %2;" : "=r"(r) : "r"(v), "r"(mask));
    return r;
}

__device__ __forceinline__ void mbar_init_(uint32_t mb, uint32_t cnt) {
    asm volatile("mbarrier.init.shared.b64 [%0], %1;" :: "r"(mb), "r"(cnt) : "memory");
}
__device__ __forceinline__ void mbar_expect_(uint32_t mb, uint32_t bytes) {
    asm volatile("mbarrier.arrive.expect_tx.shared.b64 _, [%0], %1;" :: "r"(mb), "r"(bytes) : "memory");
}
__device__ __forceinline__ void mbar_wait_(uint32_t mb, uint32_t parity) {
    uint32_t done;
    asm volatile(
        "{\n\t.reg .pred p;\n\t"
        "mbarrier.try_wait.parity.acquire.cta.shared::cta.b64 p, [%1], %2;\n\t"
        "selp.b32 %0, 1, 0, p;\n\t}"
        : "=r"(done) : "r"(mb), "r"(parity) : "memory");
    if (!done) {
        asm volatile(
            "{\n\t.reg .pred P1;\n\t"
            "WL_%=:\n\t"
            "mbarrier.try_wait.parity.acquire.cta.shared::cta.b64 P1, [%0], %1, 0x989680;\n\t"
            "@P1 bra.uni WD_%=;\n\t"
            "bra.uni WL_%=;\n\t"
            "WD_%=:\n\t}"
            :: "r"(mb), "r"(parity) : "memory");
    }
}
// async 4-byte store into a peer CTA's SMEM, tx-counted on the peer's mbarrier
__device__ __forceinline__ void st_async_f32(uint32_t addr, float v, uint32_t mb) {
    asm volatile("st.async.shared::cluster.mbarrier::complete_tx::bytes.b32 [%0], %1, [%2];"
                 :: "r"(addr), "f"(v), "r"(mb) : "memory");
}

// ---------------- main kernel: one cluster (8 CTAs) per batch ----------------
// R7 transport (converged warp-wide try_wait, triple-buffered sV, scalar
// st.async from lanes 0..7) + vv-fold (register mux tree) + Sigma-w fold
// + fixed-point REDUX reduction replacing the 4-level shfl butterfly.
__global__ void __cluster_dims__(RANKS, 1, 1) __launch_bounds__(NTH, 1)
ltc_main(const float* __restrict__ x, const float* __restrict__ h0,
         const float* __restrict__ ow, const float* __restrict__ ob,
         float* __restrict__ out)
{
    __shared__ __align__(16) float sV[3][U_];   // triple-buffered v-sets
    __shared__ float sX[T_][C_];                // full input slice for this batch (32 KB)
    __shared__ __align__(8) uint64_t mbar[3];

    const int tid  = threadIdx.x;
    const int b    = blockIdx.x / RANKS;
    const int rank = blockIdx.x % RANKS;
    const int jj   = tid >> 4;         // local post-neuron (0..15)
    const int s    = tid & 15;         // lane within j-group (0..15)
    const int jg   = rank * JPC + jj;  // global post-neuron

    // ---- weights into registers (live across entire run) ----
    float rs[IPL], rc[IPL], rw[IPL], arw[IPL];
    float crn = 0.f, crd = 0.f;        // Sigma rw, Sigma |rw| (per-lane constants)
    #pragma unroll
    for (int k = 0; k < IPL; k++) {
        int idx = (s * IPL + k) * U_ + jg;
        rs[k] = g_rsK[idx]; rc[k] = g_rcK[idx]; rw[k] = g_rwE[idx];
        arw[k] = fabsf(rw[k]);
        crn += rw[k]; crd += arw[k];
    }
    float ssk[CPL], sck[CPL], swe[CPL];
    #pragma unroll
    for (int k = 0; k < CPL; k++) {
        int idx = (s * CPL + k) * U_ + jg;
        ssk[k] = g_ssK[idx]; sck[k] = g_scK[idx]; swe[k] = g_swE[idx];
    }
    const float pcm = g_cmt[jg], pcc = g_CC[jg];
    const float pae = g_AA[jg] + EPS_;
    const float pow_ = ow[jg], pob_ = ob[jg];
    // lane whose vi-range [8s, 8s+8) contains jg: s == jg>>3
    const bool foldLane = (s == (jg >> 3));
    const int  foldIdx  = jj & 7;      // position of v_j within that lane's 8 vi's
    // 16-lane segment mask for redux (low/high half of the warp)
    const uint32_t gmask = (tid & 16) ? 0xFFFF0000u : 0x0000FFFFu;

    // stage x[b] into SMEM (float4)
    {
        const float4* xg = (const float4*)(x + (size_t)b * T_ * C_);
        float4* xs = (float4*)&sX[0][0];
        #pragma unroll 4
        for (int i = tid; i < T_ * C_ / 4; i += NTH) xs[i] = xg[i];
    }
    if (tid < U_) sV[0][tid] = h0[b * U_ + tid];   // v-set 0

    const uint32_t mbL[3] = { smem_u32(&mbar[0]), smem_u32(&mbar[1]), smem_u32(&mbar[2]) };
    if (tid == 0) {
        #pragma unroll
        for (int m = 0; m < 3; m++) { mbar_init_(mbL[m], 1); mbar_expect_(mbL[m], TX_V); }
    }
    __syncthreads();
    cluster_sync_();                   // all mbarriers armed before any st.async

    // remote addresses: lanes 0..7 of each group deliver the group's v to rank s
    uint32_t addrV[3], mbR[3];
    const uint32_t destRank = (uint32_t)(s & 7);
    #pragma unroll
    for (int m = 0; m < 3; m++) {
        addrV[m] = mapa_u32(smem_u32(&sV[m][jg]), destRank);
        mbR[m]   = mapa_u32(mbL[m], destRank);
    }
    const bool sender = (s < 8);

    uint32_t ph[3] = { 0, 0, 0 };
    float vlast = 0.f;

    for (int t = 0; t < T_; t++) {
        // ---- sensory partials (local; overlapped with prior send's transit) ----
        float xn = 0.f, xd = 0.f;
        #pragma unroll
        for (int k = 0; k < CPL; k++) {
            float xv = sX[t][s * CPL + k];
            float tt = tanhf_a(fmaf(ssk[k], xv, sck[k]));
            float p  = fmaf(swe[k], tt, swe[k]);   // w_pos*erev*sigmoid
            xn += p; xd += fabsf(p);
        }
        // pre-bias with Sigma-w constants: rn/rd loop needs only 2 FMA per k
        const float xnc = xn + crn;
        const float xdc = xd + crd;

        #pragma unroll
        for (int u = 0; u < UNFOLDS; u++) {
            const int m  = u % 3;            // buffer holding v-set 6t+u
            const int mw = (u + 1) % 3;      // buffer receiving v-set 6t+u+1
            const bool waited = (u != 0 || t != 0);
            if (waited) {
                mbar_wait_(mbL[m], ph[m]); ph[m] ^= 1;       // converged warp-wide wait
            }
            // recurrent partial over my 8 pre-neurons (sensory + Sigma-w folded in)
            float rn = xnc, rd = xdc;
            const float4* vb = (const float4*)&sV[m][s * IPL];
            float4 v0 = vb[0], v1 = vb[1];
            const float vi[IPL] = { v0.x, v0.y, v0.z, v0.w, v1.x, v1.y, v1.z, v1.w };
            #pragma unroll
            for (int k = 0; k < IPL; k++) {
                float tt = tanhf_a(fmaf(rs[k], vi[k], rc[k]));
                rn = fmaf(rw[k],  tt, rn);
                rd = fmaf(arw[k], tt, rd);
            }
            // vv-fold: register-only mux tree selects v_j (no dynamic indexing!)
            {
                float lo01 = (foldIdx & 1) ? v0.y : v0.x;
                float lo23 = (foldIdx & 1) ? v0.w : v0.z;
                float hi01 = (foldIdx & 1) ? v1.y : v1.x;
                float hi23 = (foldIdx & 1) ? v1.w : v1.z;
                float lo   = (foldIdx & 2) ? lo23 : lo01;
                float hi   = (foldIdx & 2) ? hi23 : hi01;
                float vsel = (foldIdx & 4) ? hi : lo;
                if (foldLane) {
                    rn += fmaf(pcm, vsel, pcc);
                    rd += pae;
                }
            }
            // 16-lane reduction via fixed-point REDUX (scale cancels in the ratio)
            int irn = __float2int_rn(rn * FXS);
            int ird = __float2int_rn(rd * FXS);
            irn = redux_add_s32(irn, gmask);
            ird = redux_add_s32(ird, gmask);
            float vnew = (float)irn * rcpf_((float)ird);
            // broadcast: lanes 0..7 send this group's v to all 8 ranks (skip final set)
            if (sender && (t != T_ - 1 || u != UNFOLDS - 1))
                st_async_f32(addrV[mw], vnew, mbR[mw]);
            // deferred re-arm: off the wait->send critical path (>=2 round-trips slack)
            if (waited && tid == 0) mbar_expect_(mbL[m], TX_V);
            if (u == UNFOLDS - 1) {
                if (s == 0) out[((size_t)b * T_ + t) * U_ + jg] = fmaf(vnew, pow_, pob_);
                vlast = vnew;
            }
        }
    }
    if (s == 0) out[(size_t)B_ * T_ * U_ + b * U_ + jg] = vlast;   // h_final
    cluster_sync_();   // no CTA exits while peers may still store into its SMEM
}

// ---------------- launch ----------------
extern "C" void kernel_launch(void* const* d_in, const int* in_sizes, int n_in,
                              void* d_out, int out_size)
{
    const float* x     = (const float*)d_in[0];
    const float* h0    = (const float*)d_in[1];
    const float* gleak = (const float*)d_in[2];
    const float* vleak = (const float*)d_in[3];
    const float* cm    = (const float*)d_in[4];
    const float* sigma = (const float*)d_in[5];
    const float* mu    = (const float*)d_in[6];
    const float* w     = (const float*)d_in[7];
    const float* erev  = (const float*)d_in[8];
    const float* ssig  = (const float*)d_in[9];
    const float* smu   = (const float*)d_in[10];
    const float* sw    = (const float*)d_in[11];
    const float* serev = (const float*)d_in[12];
    const float* iw    = (const float*)d_in[13];
    const float* ib    = (const float*)d_in[14];
    const float* ow    = (const float*)d_in[15];
    const float* ob    = (const float*)d_in[16];

    ltc_prep<<<64, 256>>>(sigma, mu, w, erev, ssig, smu, sw, serev, iw, ib, gleak, vleak, cm);
    ltc_main<<<B_ * RANKS, NTH>>>(x, h0, ow, ob, (float*)d_out);
}

// round 17
// speedup vs baseline: 1.3603x; 1.3603x over previous
#include <cuda_runtime.h>
#include <cstdint>

#define U_ 128
#define C_ 64
#define B_ 16
#define T_ 128
#define RANKS 8          // CTAs per cluster (one cluster per batch)
#define JPC 16           // post-neurons owned per CTA
#define IPL 8            // pre-neurons per lane (128 / 16)
#define CPL 4            // sensory channels per lane (64 / 16)
#define NTH 256
#define UNFOLDS 6
#define EPS_ 1e-8f
#define TX_V 512u        // bytes per v-set arriving at each CTA: 128 msgs * 4B

// ---------------- device scratch (no allocations allowed) ----------------
__device__ float g_rsK[U_*U_];   //  sigma * 0.5
__device__ float g_rcK[U_*U_];   // -sigma * mu * 0.5
__device__ float g_rwE[U_*U_];   //  softplus(w) * erev * 0.5
__device__ float g_ssK[C_*U_];   //  ssigma * iw * 0.5
__device__ float g_scK[C_*U_];   //  ssigma * (ib - smu) * 0.5
__device__ float g_swE[C_*U_];   //  softplus(sw) * serev * 0.5
__device__ float g_cmt[U_];      //  softplus(cm) * 6
__device__ float g_AA[U_];       //  cmt + softplus(gleak)
__device__ float g_CC[U_];       //  softplus(gleak) * vleak

__device__ __forceinline__ float softplus_f(float x) {
    return fmaxf(x, 0.0f) + log1pf(expf(-fabsf(x)));
}

__global__ void ltc_prep(const float* __restrict__ sigma, const float* __restrict__ mu,
                         const float* __restrict__ w,     const float* __restrict__ erev,
                         const float* __restrict__ ssig,  const float* __restrict__ smu,
                         const float* __restrict__ sw,    const float* __restrict__ serev,
                         const float* __restrict__ iw,    const float* __restrict__ ib,
                         const float* __restrict__ gleak, const float* __restrict__ vleak,
                         const float* __restrict__ cm)
{
    int idx = blockIdx.x * blockDim.x + threadIdx.x;
    if (idx < U_*U_) {
        float sg = sigma[idx];
        g_rsK[idx] =  sg * 0.5f;
        g_rcK[idx] = -sg * mu[idx] * 0.5f;
        g_rwE[idx] =  softplus_f(w[idx]) * erev[idx] * 0.5f;
    }
    if (idx < C_*U_) {
        int c = idx / U_;
        float sg = ssig[idx];
        g_ssK[idx] = sg * iw[c] * 0.5f;
        g_scK[idx] = sg * (ib[c] - smu[idx]) * 0.5f;
        g_swE[idx] = softplus_f(sw[idx]) * serev[idx] * 0.5f;
    }
    if (idx < U_) {
        float gl  = softplus_f(gleak[idx]);
        float cmt = softplus_f(cm[idx]) * (float)UNFOLDS;
        g_cmt[idx] = cmt;
        g_AA[idx]  = cmt + gl;
        g_CC[idx]  = gl * vleak[idx];
    }
}

// ---------------- PTX helpers ----------------
__device__ __forceinline__ uint32_t smem_u32(const void* p) {
    uint32_t a;
    asm("{ .reg .u64 t; cvta.to.shared.u64 t, %1; cvt.u32.u64 %0, t; }" : "=r"(a) : "l"(p));
    return a;
}
__device__ __forceinline__ uint32_t mapa_u32(uint32_t a, uint32_t r) {
    uint32_t o;
    asm("mapa.shared::cluster.u32 %0, %1, %2;" : "=r"(o) : "r"(a), "r"(r));
    return o;
}
__device__ __forceinline__ void cluster_sync_() {
    asm volatile("barrier.cluster.arrive.aligned;" ::: "memory");
    asm volatile("barrier.cluster.wait.aligned;"   ::: "memory");
}
__device__ __forceinline__ float tanhf_a(float x) { float y; asm("tanh.approx.f32 %0, %1;" : "=f"(y) : "f"(x)); return y; }
__device__ __forceinline__ float rcpf_(float x)   { float y; asm("rcp.approx.f32 %0, %1;"  : "=f"(y) : "f"(x)); return y; }

__device__ __forceinline__ void mbar_init_(uint32_t mb, uint32_t cnt) {
    asm volatile("mbarrier.init.shared.b64 [%0], %1;" :: "r"(mb), "r"(cnt) : "memory");
}
__device__ __forceinline__ void mbar_expect_(uint32_t mb, uint32_t bytes) {
    asm volatile("mbarrier.arrive.expect_tx.shared.b64 _, [%0], %1;" :: "r"(mb), "r"(bytes) : "memory");
}
__device__ __forceinline__ void mbar_wait_(uint32_t mb, uint32_t parity) {
    uint32_t done;
    asm volatile(
        "{\n\t.reg .pred p;\n\t"
        "mbarrier.try_wait.parity.acquire.cta.shared::cta.b64 p, [%1], %2;\n\t"
        "selp.b32 %0, 1, 0, p;\n\t}"
        : "=r"(done) : "r"(mb), "r"(parity) : "memory");
    if (!done) {
        asm volatile(
            "{\n\t.reg .pred P1;\n\t"
            "WL_%=:\n\t"
            "mbarrier.try_wait.parity.acquire.cta.shared::cta.b64 P1, [%0], %1, 0x989680;\n\t"
            "@P1 bra.uni WD_%=;\n\t"
            "bra.uni WL_%=;\n\t"
            "WD_%=:\n\t}"
            :: "r"(mb), "r"(parity) : "memory");
    }
}
// async 4-byte store into a peer CTA's SMEM, tx-counted on the peer's mbarrier
__device__ __forceinline__ void st_async_f32(uint32_t addr, float v, uint32_t mb) {
    asm volatile("st.async.shared::cluster.mbarrier::complete_tx::bytes.b32 [%0], %1, [%2];"
                 :: "r"(addr), "f"(v), "r"(mb) : "memory");
}

// ---------------- main kernel: one cluster (8 CTAs) per batch ----------------
// R14 baseline (best known: R7 transport + vv-fold via register mux tree),
// with the 4-level binary shfl butterfly replaced by a 2-level 4-ary shuffle
// tree (masks 1,2,3 then 4,8,12): ~80 cyc reduction latency vs ~120.
__global__ void __cluster_dims__(RANKS, 1, 1) __launch_bounds__(NTH, 1)
ltc_main(const float* __restrict__ x, const float* __restrict__ h0,
         const float* __restrict__ ow, const float* __restrict__ ob,
         float* __restrict__ out)
{
    __shared__ __align__(16) float sV[3][U_];   // triple-buffered v-sets
    __shared__ float sX[T_][C_];                // full input slice for this batch (32 KB)
    __shared__ __align__(8) uint64_t mbar[3];

    const int tid  = threadIdx.x;
    const int b    = blockIdx.x / RANKS;
    const int rank = blockIdx.x % RANKS;
    const int jj   = tid >> 4;         // local post-neuron (0..15)
    const int s    = tid & 15;         // lane within j-group (0..15)
    const int jg   = rank * JPC + jj;  // global post-neuron

    // ---- weights into registers (live across entire run) ----
    float rs[IPL], rc[IPL], rw[IPL];
    #pragma unroll
    for (int k = 0; k < IPL; k++) {
        int idx = (s * IPL + k) * U_ + jg;
        rs[k] = g_rsK[idx]; rc[k] = g_rcK[idx]; rw[k] = g_rwE[idx];
    }
    float ssk[CPL], sck[CPL], swe[CPL];
    #pragma unroll
    for (int k = 0; k < CPL; k++) {
        int idx = (s * CPL + k) * U_ + jg;
        ssk[k] = g_ssK[idx]; sck[k] = g_scK[idx]; swe[k] = g_swE[idx];
    }
    const float pcm = g_cmt[jg], pcc = g_CC[jg];
    const float pae = g_AA[jg] + EPS_;
    const float pow_ = ow[jg], pob_ = ob[jg];
    // lane whose vi-range [8s, 8s+8) contains jg: s == jg>>3
    const bool foldLane = (s == (jg >> 3));
    const int  foldIdx  = jj & 7;      // position of v_j within that lane's 8 vi's

    // stage x[b] into SMEM (float4)
    {
        const float4* xg = (const float4*)(x + (size_t)b * T_ * C_);
        float4* xs = (float4*)&sX[0][0];
        #pragma unroll 4
        for (int i = tid; i < T_ * C_ / 4; i += NTH) xs[i] = xg[i];
    }
    if (tid < U_) sV[0][tid] = h0[b * U_ + tid];   // v-set 0

    const uint32_t mbL[3] = { smem_u32(&mbar[0]), smem_u32(&mbar[1]), smem_u32(&mbar[2]) };
    if (tid == 0) {
        #pragma unroll
        for (int m = 0; m < 3; m++) { mbar_init_(mbL[m], 1); mbar_expect_(mbL[m], TX_V); }
    }
    __syncthreads();
    cluster_sync_();                   // all mbarriers armed before any st.async

    // remote addresses: lanes 0..7 of each group deliver the group's v to rank s
    uint32_t addrV[3], mbR[3];
    const uint32_t destRank = (uint32_t)(s & 7);
    #pragma unroll
    for (int m = 0; m < 3; m++) {
        addrV[m] = mapa_u32(smem_u32(&sV[m][jg]), destRank);
        mbR[m]   = mapa_u32(mbL[m], destRank);
    }
    const bool sender = (s < 8);

    uint32_t ph[3] = { 0, 0, 0 };
    float vlast = 0.f;

    for (int t = 0; t < T_; t++) {
        // ---- sensory partials (local; overlapped with prior send's transit) ----
        float xn = 0.f, xd = 0.f;
        #pragma unroll
        for (int k = 0; k < CPL; k++) {
            float xv = sX[t][s * CPL + k];
            float tt = tanhf_a(fmaf(ssk[k], xv, sck[k]));
            float p  = fmaf(swe[k], tt, swe[k]);   // w_pos*erev*sigmoid
            xn += p; xd += fabsf(p);
        }

        #pragma unroll
        for (int u = 0; u < UNFOLDS; u++) {
            const int m  = u % 3;            // buffer holding v-set 6t+u
            const int mw = (u + 1) % 3;      // buffer receiving v-set 6t+u+1
            if (u != 0 || t != 0) {
                mbar_wait_(mbL[m], ph[m]); ph[m] ^= 1;       // converged warp-wide wait
                if (tid == 0) mbar_expect_(mbL[m], TX_V);    // immediate re-arm
            }
            // recurrent partial over my 8 pre-neurons (sensory folded in)
            float rn = xn, rd = xd;
            const float4* vb = (const float4*)&sV[m][s * IPL];
            float4 v0 = vb[0], v1 = vb[1];
            const float vi[IPL] = { v0.x, v0.y, v0.z, v0.w, v1.x, v1.y, v1.z, v1.w };
            #pragma unroll
            for (int k = 0; k < IPL; k++) {
                float tt = tanhf_a(fmaf(rs[k], vi[k], rc[k]));
                float p  = fmaf(rw[k], tt, rw[k]);
                rn += p; rd += fabsf(p);
            }
            // vv-fold: register-only mux tree selects v_j (no dynamic indexing!)
            {
                float lo01 = (foldIdx & 1) ? v0.y : v0.x;
                float lo23 = (foldIdx & 1) ? v0.w : v0.z;
                float hi01 = (foldIdx & 1) ? v1.y : v1.x;
                float hi23 = (foldIdx & 1) ? v1.w : v1.z;
                float lo   = (foldIdx & 2) ? lo23 : lo01;
                float hi   = (foldIdx & 2) ? hi23 : hi01;
                float vsel = (foldIdx & 4) ? hi : lo;
                if (foldLane) {
                    rn += fmaf(pcm, vsel, pcc);
                    rd += pae;
                }
            }
            // 2-level 4-ary shuffle tree over the 16-lane group (~80 cyc vs ~120)
            {
                float a1 = __shfl_xor_sync(0xffffffffu, rn, 1);
                float a2 = __shfl_xor_sync(0xffffffffu, rn, 2);
                float a3 = __shfl_xor_sync(0xffffffffu, rn, 3);
                float b1 = __shfl_xor_sync(0xffffffffu, rd, 1);
                float b2 = __shfl_xor_sync(0xffffffffu, rd, 2);
                float b3 = __shfl_xor_sync(0xffffffffu, rd, 3);
                rn = (rn + a1) + (a2 + a3);
                rd = (rd + b1) + (b2 + b3);
                float c1 = __shfl_xor_sync(0xffffffffu, rn, 4);
                float c2 = __shfl_xor_sync(0xffffffffu, rn, 8);
                float c3 = __shfl_xor_sync(0xffffffffu, rn, 12);
                float d1 = __shfl_xor_sync(0xffffffffu, rd, 4);
                float d2 = __shfl_xor_sync(0xffffffffu, rd, 8);
                float d3 = __shfl_xor_sync(0xffffffffu, rd, 12);
                rn = (rn + c1) + (c2 + c3);
                rd = (rd + d1) + (d2 + d3);
            }
            float vnew = rn * rcpf_(rd);
            // broadcast: lanes 0..7 send this group's v to all 8 ranks (skip final set)
            if (sender && (t != T_ - 1 || u != UNFOLDS - 1))
                st_async_f32(addrV[mw], vnew, mbR[mw]);
            if (u == UNFOLDS - 1) {
                if (s == 0) out[((size_t)b * T_ + t) * U_ + jg] = fmaf(vnew, pow_, pob_);
                vlast = vnew;
            }
        }
    }
    if (s == 0) out[(size_t)B_ * T_ * U_ + b * U_ + jg] = vlast;   // h_final
    cluster_sync_();   // no CTA exits while peers may still store into its SMEM
}

// ---------------- launch ----------------
extern "C" void kernel_launch(void* const* d_in, const int* in_sizes, int n_in,
                              void* d_out, int out_size)
{
    const float* x     = (const float*)d_in[0];
    const float* h0    = (const float*)d_in[1];
    const float* gleak = (const float*)d_in[2];
    const float* vleak = (const float*)d_in[3];
    const float* cm    = (const float*)d_in[4];
    const float* sigma = (const float*)d_in[5];
    const float* mu    = (const float*)d_in[6];
    const float* w     = (const float*)d_in[7];
    const float* erev  = (const float*)d_in[8];
    const float* ssig  = (const float*)d_in[9];
    const float* smu   = (const float*)d_in[10];
    const float* sw    = (const float*)d_in[11];
    const float* serev = (const float*)d_in[12];
    const float* iw    = (const float*)d_in[13];
    const float* ib    = (const float*)d_in[14];
    const float* ow    = (const float*)d_in[15];
    const float* ob    = (const float*)d_in[16];

    ltc_prep<<<64, 256>>>(sigma, mu, w, erev, ssig, smu, sw, serev, iw, ib, gleak, vleak, cm);
    ltc_main<<<B_ * RANKS, NTH>>>(x, h0, ow, ob, (float*)d_out);
}